// round 6
// baseline (speedup 1.0000x reference)
#include <cuda_runtime.h>
#include <math.h>

#define NB 252
#define THREADS 256
#define BATCH 64
#define NPG 9
#define NTOT (BATCH*NPG)   // 576
#define H 128
#define K1 1801
#define O1 900
#define O2 100
#define ASL 243
#define NT1 15             // 15 n-tiles x 64 outs
#define KS1 12
#define KC1 151            // 12*151 = 1812 >= 1801
#define KS2 16
#define KC2 57             // 16*57 = 912 >= 900

// scratch (no allocation allowed)
__device__ float g_s1_part[KS1 * BATCH * O1];
__device__ float g_s2_part[KS2 * BATCH * O2];
__device__ float g_Ai[NTOT * H];
__device__ float g_Bj[NTOT * H];
__device__ unsigned g_count = 0;
__device__ unsigned g_gen = 0;

__device__ __forceinline__ void grid_barrier() {
    __syncthreads();
    __threadfence();
    if (threadIdx.x == 0) {
        unsigned gen = *(volatile unsigned*)&g_gen;
        if (atomicAdd(&g_count, 1u) == NB - 1) {
            g_count = 0;
            __threadfence();
            atomicAdd(&g_gen, 1u);
        } else {
            while (*(volatile unsigned*)&g_gen == gen) __nanosleep(32);
        }
    }
    __syncthreads();
}

// One 32-row x 64-col tile of [Ai|Bj] = relu(nf) @ Wa2[0:256 rows]  (256 thr)
__device__ __forceinline__ void ab_task(int task, int t, float* buf,
                                        const float* __restrict__ nf,
                                        const float* __restrict__ Wa2) {
    float (*As)[128] = (float (*)[128])buf;            // 32x128
    float (*Bs)[64]  = (float (*)[64])(buf + 4096);    // 128x64
    const int mt = task % 18, nty = task / 18;
    const int m0 = mt * 32;
    const int n0 = nty * 64;
    const int woff = (nty >= 2) ? (H * H - H) : 0;
    for (int idx = t; idx < 32 * 128; idx += THREADS) {
        int r = idx >> 7, k = idx & 127;
        As[r][k] = fmaxf(nf[(m0 + r) * H + k], 0.f);
    }
    for (int idx = t; idx < 128 * 64; idx += THREADS) {
        int k = idx >> 6, c = idx & 63;
        Bs[k][c] = Wa2[k * H + n0 + c + woff];
    }
    __syncthreads();
    const int c = t & 63, r0 = t >> 6;   // r0 in 0..3, rows r0+4i
    float acc[8];
#pragma unroll
    for (int i = 0; i < 8; i++) acc[i] = 0.f;
#pragma unroll 8
    for (int k = 0; k < 128; k += 4) {
        float b0v = Bs[k][c], b1v = Bs[k + 1][c];
        float b2v = Bs[k + 2][c], b3v = Bs[k + 3][c];
#pragma unroll
        for (int i = 0; i < 8; i++) {
            float4 a = *(const float4*)&As[r0 + 4 * i][k];
            acc[i] += a.x * b0v + a.y * b1v + a.z * b2v + a.w * b3v;
        }
    }
    float* dst = (nty < 2) ? g_Ai : g_Bj;
    const int col = (nty < 2) ? (n0 + c) : (n0 - 128 + c);
#pragma unroll
    for (int i = 0; i < 8; i++)
        dst[(m0 + r0 + 4 * i) * H + col] = acc[i];
}

__global__ __launch_bounds__(THREADS, 2)
void fused_kernel(const float* __restrict__ nf, const float* __restrict__ spec,
                  const float* __restrict__ mask, const int* __restrict__ imask,
                  const float* __restrict__ W1, const float* __restrict__ b1,
                  const float* __restrict__ W2, const float* __restrict__ b2,
                  const float* __restrict__ Wv1, const float* __restrict__ bv1,
                  const float* __restrict__ Wv2, const float* __restrict__ bv2,
                  const float* __restrict__ Wa2, const float* __restrict__ ba2,
                  const float* __restrict__ Wf, const float* __restrict__ bf,
                  float* __restrict__ out) {
    __shared__ __align__(16) float buf[12288];   // 48KB, reused per phase
    const int t = threadIdx.x;
    const int bid = blockIdx.x;

    // ========== Phase 1: gemm1 (180 blocks) + ab gemm (72 blocks, 1 task each) ====
    if (bid < NT1 * KS1) {
        // block: 64 batches x 64 outs; thread: 8 batches x 2 outs (16 acc)
        const int nt = bid / KS1, ks = bid % KS1;
        const int og = t & 31;
        const int bg = t >> 5;               // 0..7
        const int o0 = nt * 64 + og * 2;
        const int b0 = bg * 8;
        const int kbeg = ks * KC1;
        const int kend = min(kbeg + KC1, K1);
        const int nch = (kend - kbeg + 31) >> 5;
        float* sp = buf;                     // [32][68] k-major spec tile
        float* wt = buf + 32 * 68;           // [32][68] k-major weight tile

        // staging coords (8 elems each, per array)
        const int kk_s = t & 31;             // spec: lane = k (coalesced)
        const int bb_s = t >> 5;             // + 8j
        const int kk_w = t >> 6;             // + 4j
        const int oo_w = t & 63;
        const int ow_g = nt * 64 + oo_w;
        const bool wok = (ow_g < O1);

        float rs[8], rw[8];
        {   // prefetch chunk 0
            const int k0 = kbeg;
            const int klen = kend - k0;
#pragma unroll
            for (int j = 0; j < 8; j++)
                rs[j] = (kk_s < klen) ? spec[(bb_s + 8 * j) * K1 + k0 + kk_s] : 0.f;
#pragma unroll
            for (int j = 0; j < 8; j++) {
                int kk = kk_w + 4 * j;
                rw[j] = (kk < klen && wok) ? W1[(k0 + kk) * O1 + ow_g] : 0.f;
            }
        }
        float acc[8][2];
#pragma unroll
        for (int n = 0; n < 8; n++) { acc[n][0] = 0.f; acc[n][1] = 0.f; }

        for (int c = 0; c < nch; c++) {
            __syncthreads();
#pragma unroll
            for (int j = 0; j < 8; j++)
                sp[kk_s * 68 + bb_s + 8 * j] = rs[j];
#pragma unroll
            for (int j = 0; j < 8; j++)
                wt[(kk_w + 4 * j) * 68 + oo_w] = rw[j];
            __syncthreads();
            if (c + 1 < nch) {   // prefetch next chunk while computing
                const int k0 = kbeg + (c + 1) * 32;
                const int klen = kend - k0;
#pragma unroll
                for (int j = 0; j < 8; j++)
                    rs[j] = (kk_s < klen) ? spec[(bb_s + 8 * j) * K1 + k0 + kk_s] : 0.f;
#pragma unroll
                for (int j = 0; j < 8; j++) {
                    int kk = kk_w + 4 * j;
                    rw[j] = (kk < klen && wok) ? W1[(k0 + kk) * O1 + ow_g] : 0.f;
                }
            }
#pragma unroll
            for (int kk = 0; kk < 32; kk++) {
                float4 s0 = *(const float4*)(sp + kk * 68 + b0);
                float4 s1 = *(const float4*)(sp + kk * 68 + b0 + 4);
                float2 w2 = *(const float2*)(wt + kk * 68 + og * 2);
                acc[0][0] += s0.x * w2.x; acc[0][1] += s0.x * w2.y;
                acc[1][0] += s0.y * w2.x; acc[1][1] += s0.y * w2.y;
                acc[2][0] += s0.z * w2.x; acc[2][1] += s0.z * w2.y;
                acc[3][0] += s0.w * w2.x; acc[3][1] += s0.w * w2.y;
                acc[4][0] += s1.x * w2.x; acc[4][1] += s1.x * w2.y;
                acc[5][0] += s1.y * w2.x; acc[5][1] += s1.y * w2.y;
                acc[6][0] += s1.z * w2.x; acc[6][1] += s1.z * w2.y;
                acc[7][0] += s1.w * w2.x; acc[7][1] += s1.w * w2.y;
            }
        }
        float* dst = g_s1_part + ks * (BATCH * O1);
        if (o0 + 1 < O1) {
#pragma unroll
            for (int n = 0; n < 8; n++) {
                dst[(b0 + n) * O1 + o0] = acc[n][0];
                dst[(b0 + n) * O1 + o0 + 1] = acc[n][1];
            }
        } else if (o0 < O1) {
#pragma unroll
            for (int n = 0; n < 8; n++)
                dst[(b0 + n) * O1 + o0] = acc[n][0];
        }
    } else {
        ab_task(bid - NT1 * KS1, t, buf, nf, Wa2);   // 72 tasks, one per block
    }

    grid_barrier();

    // ========== Phase 2: reduce(gemm1) -> gemm2 split-K (64 blocks) ==========
    if (bid < 64) {
        const int nt = bid & 3, ks = bid >> 2;   // 4 o-tiles x 16 k-splits
        const int o = nt * 32 + (t & 31);
        const int bg = t >> 5;                    // 0..7, 8 batches each
        const int b0 = bg * 8;
        const int kbeg = ks * KC2;
        const int kend = min(kbeg + KC2, O1);
        const int klen = kend - kbeg;
        float* s1r = buf;                         // [64][60]
        for (int idx = t; idx < 64 * KC2; idx += THREADS) {
            int b = idx / KC2, kk = idx - b * KC2;
            float v = 0.f;
            if (kk < klen) {
                int gk = kbeg + kk;
                v = b1[gk];
#pragma unroll
                for (int c = 0; c < KS1; c++)
                    v += g_s1_part[c * (BATCH * O1) + b * O1 + gk];
                v = fmaxf(v, 0.f);
            }
            s1r[b * 60 + kk] = v;
        }
        __syncthreads();
        float acc[8];
#pragma unroll
        for (int n = 0; n < 8; n++) acc[n] = 0.f;
        const float* sb = s1r + b0 * 60;
        for (int kk = 0; kk < klen; kk++) {
            float w = (o < O2) ? W2[(kbeg + kk) * O2 + o] : 0.f;
#pragma unroll
            for (int n = 0; n < 8; n++)
                acc[n] += sb[n * 60 + kk] * w;
        }
        if (o < O2) {
#pragma unroll
            for (int n = 0; n < 8; n++)
                g_s2_part[ks * (BATCH * O2) + (b0 + n) * O2 + o] = acc[n];
        }
    }

    grid_barrier();

    // ========== Phase 3: per-graph ss -> D -> value -> pair -> softmax ==========
    if (bid < 64) {
        const int b = bid;
        const int lane = t & 31, w = t >> 5;
        float* ss  = buf;            // 100
        float* Dc  = buf + 128;      // 128
        float* x   = buf + 256;      // 228
        float* hred= buf + 512;      // 64
        float* As  = buf + 640;      // 9*132
        float* Bs  = buf + 1856;     // 9*132
        float* Wft = buf + 3072;     // 3*128 (bond-major)
        float* fp  = buf + 3456;     // 243
        float* red = buf + 3712;     // 8
        float* rs2 = buf + 3728;     // rmax, rsum

        if (t < O2) {
            float a = b2[t];
#pragma unroll
            for (int c = 0; c < KS2; c++)
                a += g_s2_part[c * (BATCH * O2) + b * O2 + t];
            ss[t] = fmaxf(a, 0.f);
        }
        __syncthreads();

        if (t < H) {
            float d = ba2[t];
#pragma unroll 4
            for (int k = 0; k < O2; k++)
                d += ss[k] * Wa2[(2 * H + k) * H + t];
            Dc[t] = d;
            float sum = 0.f;
#pragma unroll
            for (int i = 0; i < NPG; i++) sum += nf[(b * NPG + i) * H + t];
            x[t] = sum;
        }
        if (t >= H && t < H + O2) x[t] = ss[t - H];
        for (int idx = t; idx < NPG * H; idx += THREADS) {
            int i = idx >> 7, h = idx & 127;
            As[i * 132 + h] = g_Ai[(b * NPG + i) * H + h];
            Bs[i * 132 + h] = g_Bj[(b * NPG + i) * H + h];
        }
        for (int idx = t; idx < H * 3; idx += THREADS)
            Wft[(idx % 3) * H + idx / 3] = Wf[idx];
        __syncthreads();

        if (t < 64) {
            float a = bv1[t];
#pragma unroll 4
            for (int k = 0; k < H + O2; k++) a += x[k] * Wv1[k * 64 + t];
            hred[t] = fmaxf(a, 0.f) * Wv2[t];
        }
        if (t < ASL) {
            const int pair = t / 3, bond = t - pair * 3;
            const int i = pair / NPG, j = pair - i * NPG;
            const float4* Ap = (const float4*)(As + i * 132);
            const float4* Bp = (const float4*)(Bs + j * 132);
            const float4* Dp = (const float4*)Dc;
            const float4* Wp = (const float4*)(Wft + bond * H);
            float a = 0.f;
#pragma unroll 8
            for (int q = 0; q < 32; q++) {
                float4 av = Ap[q], bv = Bp[q], dv = Dp[q], wv = Wp[q];
                a += fmaxf(av.x + bv.x + dv.x, 0.f) * wv.x
                   + fmaxf(av.y + bv.y + dv.y, 0.f) * wv.y
                   + fmaxf(av.z + bv.z + dv.z, 0.f) * wv.z
                   + fmaxf(av.w + bv.w + dv.w, 0.f) * wv.w;
            }
            fp[t] = a + bf[bond];
        }
        __syncthreads();

        float g = -INFINITY;
        if (t < ASL) g = fp[imask[b * ASL + t]] + mask[b * ASL + t];
        float v = g;
#pragma unroll
        for (int off = 16; off; off >>= 1) v = fmaxf(v, __shfl_xor_sync(0xffffffffu, v, off));
        if (lane == 0) red[w] = v;
        __syncthreads();
        if (t == 0) {
            float m = red[0];
#pragma unroll
            for (int i = 1; i < 8; i++) m = fmaxf(m, red[i]);
            rs2[0] = m;
        }
        __syncthreads();
        float e = (t < ASL) ? __expf(g - rs2[0]) : 0.f;
        v = e;
#pragma unroll
        for (int off = 16; off; off >>= 1) v += __shfl_xor_sync(0xffffffffu, v, off);
        if (lane == 0) red[w] = v;
        __syncthreads();
        if (t == 0) {
            float s = 0.f;
#pragma unroll
            for (int i = 0; i < 8; i++) s += red[i];
            rs2[1] = s;
            float vo = bv2[0];
#pragma unroll
            for (int k = 0; k < 64; k++) vo += hred[k];
            out[BATCH * ASL + b] = vo;
        }
        __syncthreads();
        if (t < ASL) out[b * ASL + t] = e / rs2[1];
    }
}

extern "C" void kernel_launch(void* const* d_in, const int* in_sizes, int n_in,
                              void* d_out, int out_size) {
    const float* nf   = (const float*)d_in[0];
    const float* spec = (const float*)d_in[1];
    const float* mask = (const float*)d_in[3];
    const int*   imask= (const int*)  d_in[4];
    const float* W1   = (const float*)d_in[5];
    const float* b1   = (const float*)d_in[6];
    const float* W2   = (const float*)d_in[7];
    const float* b2   = (const float*)d_in[8];
    const float* Wv1  = (const float*)d_in[9];
    const float* bv1  = (const float*)d_in[10];
    const float* Wv2  = (const float*)d_in[11];
    const float* bv2  = (const float*)d_in[12];
    const float* Wa2  = (const float*)d_in[13];
    const float* ba2  = (const float*)d_in[14];
    const float* Wf   = (const float*)d_in[15];
    const float* bf   = (const float*)d_in[16];
    float* out = (float*)d_out;

    fused_kernel<<<NB, THREADS>>>(nf, spec, mask, imask, W1, b1, W2, b2,
                                  Wv1, bv1, Wv2, bv2, Wa2, ba2, Wf, bf, out);
}

// round 7
// speedup vs baseline: 1.0831x; 1.0831x over previous
#include <cuda_runtime.h>
#include <math.h>
#include <stdint.h>

#define NB 148
#define THREADS 512
#define BATCH 64
#define NPG 9
#define NTOT (BATCH*NPG)   // 576
#define H 128
#define K1 1801
#define O1 900
#define O2 100
#define ASL 243
#define NT1 15             // 15 n-tiles x 64 outs
#define KS1 9
#define KC1 201            // 9*201 = 1809 >= 1801
#define KS2 16
#define KC2 57             // 16*57 = 912 >= 900

// scratch (no allocation allowed)
__device__ float g_s1_part[KS1 * BATCH * O1];
__device__ float g_s2_part[KS2 * BATCH * O2];
__device__ float g_Ai[NTOT * H];
__device__ float g_Bj[NTOT * H];
__device__ unsigned g_count = 0;
__device__ unsigned g_gen = 0;

__device__ __forceinline__ void grid_barrier() {
    __syncthreads();
    __threadfence();
    if (threadIdx.x == 0) {
        unsigned gen = *(volatile unsigned*)&g_gen;
        if (atomicAdd(&g_count, 1u) == NB - 1) {
            g_count = 0;
            __threadfence();
            atomicAdd(&g_gen, 1u);
        } else {
            while (*(volatile unsigned*)&g_gen == gen) __nanosleep(32);
        }
    }
    __syncthreads();
}

__device__ __forceinline__ void cpasync4(uint32_t dst, const float* src, bool p) {
    asm volatile("cp.async.ca.shared.global [%0], [%1], 4, %2;\n"
                 :: "r"(dst), "l"(src), "r"(p ? 4 : 0));
}
__device__ __forceinline__ void cpasync16(uint32_t dst, const float* src, bool p) {
    asm volatile("cp.async.cg.shared.global [%0], [%1], 16, %2;\n"
                 :: "r"(dst), "l"(src), "r"(p ? 16 : 0));
}
__device__ __forceinline__ void cpcommit() {
    asm volatile("cp.async.commit_group;\n");
}
__device__ __forceinline__ void cpwait0() {
    asm volatile("cp.async.wait_group 0;\n" ::: "memory");
}
__device__ __forceinline__ void cpwait1() {
    asm volatile("cp.async.wait_group 1;\n" ::: "memory");
}

// One 32-row x 64-col tile of [Ai|Bj] = relu(nf) @ Wa2[0:256 rows]  (512 thr)
__device__ __forceinline__ void ab_task(int task, int t, float* buf,
                                        const float* __restrict__ nf,
                                        const float* __restrict__ Wa2) {
    float (*As)[128] = (float (*)[128])buf;            // 32x128
    float (*Bs)[64]  = (float (*)[64])(buf + 4096);    // 128x64
    const int mt = task % 18, nty = task / 18;
    const int m0 = mt * 32;
    const int n0 = nty * 64;
    const int woff = (nty >= 2) ? (H * H - H) : 0;
    for (int idx = t; idx < 32 * 128; idx += THREADS) {
        int r = idx >> 7, k = idx & 127;
        As[r][k] = fmaxf(nf[(m0 + r) * H + k], 0.f);
    }
    for (int idx = t; idx < 128 * 64; idx += THREADS) {
        int k = idx >> 6, c = idx & 63;
        Bs[k][c] = Wa2[k * H + n0 + c + woff];
    }
    __syncthreads();
    const int c = t & 63, r0 = t >> 6;   // 8 row groups, rows r0+8i
    float acc[4] = {0.f, 0.f, 0.f, 0.f};
#pragma unroll 8
    for (int k = 0; k < 128; k += 4) {
        float b0v = Bs[k][c], b1v = Bs[k + 1][c];
        float b2v = Bs[k + 2][c], b3v = Bs[k + 3][c];
#pragma unroll
        for (int i = 0; i < 4; i++) {
            float4 a = *(const float4*)&As[r0 + 8 * i][k];
            acc[i] += a.x * b0v + a.y * b1v + a.z * b2v + a.w * b3v;
        }
    }
    float* dst = (nty < 2) ? g_Ai : g_Bj;
    const int col = (nty < 2) ? (n0 + c) : (n0 - 128 + c);
#pragma unroll
    for (int i = 0; i < 4; i++)
        dst[(m0 + r0 + 8 * i) * H + col] = acc[i];
}

__global__ __launch_bounds__(THREADS, 1)
void fused_kernel(const float* __restrict__ nf, const float* __restrict__ spec,
                  const float* __restrict__ mask, const int* __restrict__ imask,
                  const float* __restrict__ W1, const float* __restrict__ b1,
                  const float* __restrict__ W2, const float* __restrict__ b2,
                  const float* __restrict__ Wv1, const float* __restrict__ bv1,
                  const float* __restrict__ Wv2, const float* __restrict__ bv2,
                  const float* __restrict__ Wa2, const float* __restrict__ ba2,
                  const float* __restrict__ Wf, const float* __restrict__ bf,
                  float* __restrict__ out) {
    __shared__ __align__(16) float buf[12288];   // 48KB, reused per phase
    const int t = threadIdx.x;
    const int bid = blockIdx.x;

    // ===== Phase 1: gemm1 (135 blocks, cp.async dbl-buffer) + 13 ab tasks =====
    if (bid < NT1 * KS1) {
        const int nt = bid / KS1, ks = bid % KS1;
        const int og = t & 31;               // out-pair index (2 outs)
        const int bg = t >> 5;               // 0..15, 4 batches each
        const int o0 = nt * 64 + og * 2;
        const int b0 = bg * 4;
        const int kbeg = ks * KC1;
        const int kend = min(kbeg + KC1, K1);
        const int nch = (kend - kbeg + 31) >> 5;

        // buffers: sp[p] at p*4352, wt[p] at p*4352+2176 (floats), stride 68/row
        const uint32_t sbase = (uint32_t)__cvta_generic_to_shared(buf);

        // staging coords
        const int kk_s = t & 31;             // spec k (coalesced along k)
        const int bb_s = t >> 5;             // + 16j
        const int kk_w = t >> 4;             // W1 row 0..31
        const int c4   = (t & 15) * 4;       // W1 4-col group
        const float* wsrc0 = W1 + nt * 64 + c4;
        const bool wcol_ok = (nt * 64 + c4 + 3) < O1;  // 900%4==0 -> whole group ok or not

        // issue chunk 0
        {
            const int k0 = kbeg;
            const int klen = kend - k0;
#pragma unroll
            for (int j = 0; j < 4; j++)
                cpasync4(sbase + (kk_s * 68 + bb_s + 16 * j) * 4,
                         spec + (bb_s + 16 * j) * K1 + k0 + kk_s, kk_s < klen);
            cpasync16(sbase + (2176 + kk_w * 68 + c4) * 4,
                      wsrc0 + (size_t)(k0 + kk_w) * O1, (kk_w < klen) && wcol_ok);
            cpcommit();
        }

        float acc[8][2];
#pragma unroll
        for (int n = 0; n < 8; n++) { acc[n][0] = 0.f; acc[n][1] = 0.f; }

        for (int c = 0; c < nch; c++) {
            const int p = c & 1;
            if (c + 1 < nch) {
                const int pn = (c + 1) & 1;
                const int k0 = kbeg + (c + 1) * 32;
                const int klen = kend - k0;
#pragma unroll
                for (int j = 0; j < 4; j++)
                    cpasync4(sbase + (pn * 4352 + kk_s * 68 + bb_s + 16 * j) * 4,
                             spec + (bb_s + 16 * j) * K1 + k0 + kk_s, kk_s < klen);
                cpasync16(sbase + (pn * 4352 + 2176 + kk_w * 68 + c4) * 4,
                          wsrc0 + (size_t)(k0 + kk_w) * O1, (kk_w < klen) && wcol_ok);
                cpcommit();
                cpwait1();       // chunk c complete (c+1 may be in flight)
            } else {
                cpwait0();
            }
            __syncthreads();
            const float* sp = buf + p * 4352;
            const float* wt = sp + 2176;
#pragma unroll
            for (int kk = 0; kk < 32; kk++) {
                float4 s4 = *(const float4*)(sp + kk * 68 + b0);   // warp bcast
                float2 w2 = *(const float2*)(wt + kk * 68 + og * 2);
                acc[0][0] += s4.x * w2.x; acc[0][1] += s4.x * w2.y;
                acc[1][0] += s4.y * w2.x; acc[1][1] += s4.y * w2.y;
                acc[2][0] += s4.z * w2.x; acc[2][1] += s4.z * w2.y;
                acc[3][0] += s4.w * w2.x; acc[3][1] += s4.w * w2.y;
                float4 s5 = *(const float4*)(sp + kk * 68 + b0 + 64);  // batches b0+64.. no
                (void)s5;
                break;
            }
            // NOTE: loop body rewritten below for correctness (see full loop)
            // (the above break never executes the remaining kks)
            {
#pragma unroll
                for (int kk = 1; kk < 32; kk++) {
                    float4 s4 = *(const float4*)(sp + kk * 68 + b0);
                    float2 w2 = *(const float2*)(wt + kk * 68 + og * 2);
                    acc[0][0] += s4.x * w2.x; acc[0][1] += s4.x * w2.y;
                    acc[1][0] += s4.y * w2.x; acc[1][1] += s4.y * w2.y;
                    acc[2][0] += s4.z * w2.x; acc[2][1] += s4.z * w2.y;
                    acc[3][0] += s4.w * w2.x; acc[3][1] += s4.w * w2.y;
                }
            }
            __syncthreads();
        }
        // write 4 batches x 2 outs
        float* dst = g_s1_part + ks * (BATCH * O1);
        if (o0 < O1) {
#pragma unroll
            for (int n = 0; n < 4; n++) {
                dst[(b0 + n) * O1 + o0]     = acc[n][0];
                dst[(b0 + n) * O1 + o0 + 1] = acc[n][1];
            }
        }
    } else {
        ab_task(bid - NT1 * KS1, t, buf, nf, Wa2);   // tasks 0..12
    }

    grid_barrier();

    // ===== Phase 2: gemm2 (blocks 0-63) + ab tasks 13-71 (blocks 64-122) =====
    if (bid < 64) {
        const int nt = bid & 3, ks = bid >> 2;   // 4 o-tiles x 16 k-splits
        const int o = nt * 32 + (t & 31);
        const int bg = t >> 5;
        const int b0 = bg * 4;
        const int kbeg = ks * KC2;
        const int kend = min(kbeg + KC2, O1);
        const int klen = kend - kbeg;
        float* s1r = buf;                         // [64][60]
        for (int idx = t; idx < 64 * KC2; idx += THREADS) {
            int b = idx / KC2, kk = idx - b * KC2;
            float v = 0.f;
            if (kk < klen) {
                int gk = kbeg + kk;
                v = b1[gk];
#pragma unroll
                for (int c = 0; c < KS1; c++)
                    v += g_s1_part[c * (BATCH * O1) + b * O1 + gk];
                v = fmaxf(v, 0.f);
            }
            s1r[b * 60 + kk] = v;
        }
        __syncthreads();
        float acc[4] = {0.f, 0.f, 0.f, 0.f};
        const float* sb = s1r + b0 * 60;
        for (int kk = 0; kk < klen; kk++) {
            float w = (o < O2) ? W2[(kbeg + kk) * O2 + o] : 0.f;
            acc[0] += sb[kk] * w;
            acc[1] += sb[60 + kk] * w;
            acc[2] += sb[120 + kk] * w;
            acc[3] += sb[180 + kk] * w;
        }
        if (o < O2) {
#pragma unroll
            for (int n = 0; n < 4; n++)
                g_s2_part[ks * (BATCH * O2) + (b0 + n) * O2 + o] = acc[n];
        }
    } else if (bid < 64 + 59) {
        ab_task(13 + (bid - 64), t, buf, nf, Wa2);   // tasks 13..71
    }

    grid_barrier();

    // ===== Phase 3: per-graph ss -> D -> value -> pair -> softmax =====
    if (bid < 64) {
        const int b = bid;
        const int lane = t & 31, w = t >> 5;
        float* ss  = buf;            // 100
        float* Dc  = buf + 128;      // 128
        float* x   = buf + 256;      // 228
        float* hred= buf + 512;      // 64
        float* As  = buf + 640;      // 9*132
        float* Bs  = buf + 1856;     // 9*132
        float* Wft = buf + 3072;     // 3*128 (bond-major)
        float* fp  = buf + 3456;     // 243
        float* red = buf + 3712;     // 16
        float* rs2 = buf + 3744;     // rmax, rsum

        if (t < O2) {
            float a = b2[t];
#pragma unroll
            for (int c = 0; c < KS2; c++)
                a += g_s2_part[c * (BATCH * O2) + b * O2 + t];
            ss[t] = fmaxf(a, 0.f);
        }
        __syncthreads();

        if (t < H) {
            float d = ba2[t];
#pragma unroll 4
            for (int k = 0; k < O2; k++)
                d += ss[k] * Wa2[(2 * H + k) * H + t];
            Dc[t] = d;
            float sum = 0.f;
#pragma unroll
            for (int i = 0; i < NPG; i++) sum += nf[(b * NPG + i) * H + t];
            x[t] = sum;
        }
        if (t >= H && t < H + O2) x[t] = ss[t - H];
        for (int idx = t; idx < NPG * H; idx += THREADS) {
            int i = idx >> 7, h = idx & 127;
            As[i * 132 + h] = g_Ai[(b * NPG + i) * H + h];
            Bs[i * 132 + h] = g_Bj[(b * NPG + i) * H + h];
        }
        for (int idx = t; idx < H * 3; idx += THREADS)
            Wft[(idx % 3) * H + idx / 3] = Wf[idx];
        __syncthreads();

        if (t < 64) {
            float a = bv1[t];
#pragma unroll 4
            for (int k = 0; k < H + O2; k++) a += x[k] * Wv1[k * 64 + t];
            hred[t] = fmaxf(a, 0.f) * Wv2[t];
        }
        if (t < ASL) {
            const int pair = t / 3, bond = t - pair * 3;
            const int i = pair / NPG, j = pair - i * NPG;
            const float4* Ap = (const float4*)(As + i * 132);
            const float4* Bp = (const float4*)(Bs + j * 132);
            const float4* Dp = (const float4*)Dc;
            const float4* Wp = (const float4*)(Wft + bond * H);
            float a = 0.f;
#pragma unroll 8
            for (int q = 0; q < 32; q++) {
                float4 av = Ap[q], bv = Bp[q], dv = Dp[q], wv = Wp[q];
                a += fmaxf(av.x + bv.x + dv.x, 0.f) * wv.x
                   + fmaxf(av.y + bv.y + dv.y, 0.f) * wv.y
                   + fmaxf(av.z + bv.z + dv.z, 0.f) * wv.z
                   + fmaxf(av.w + bv.w + dv.w, 0.f) * wv.w;
            }
            fp[t] = a + bf[bond];
        }
        __syncthreads();

        float g = -INFINITY;
        if (t < ASL) g = fp[imask[b * ASL + t]] + mask[b * ASL + t];
        float v = g;
#pragma unroll
        for (int off = 16; off; off >>= 1) v = fmaxf(v, __shfl_xor_sync(0xffffffffu, v, off));
        if (lane == 0) red[w] = v;
        __syncthreads();
        if (t == 0) {
            float m = red[0];
#pragma unroll
            for (int i = 1; i < 16; i++) m = fmaxf(m, red[i]);
            rs2[0] = m;
        }
        __syncthreads();
        float e = (t < ASL) ? __expf(g - rs2[0]) : 0.f;
        v = e;
#pragma unroll
        for (int off = 16; off; off >>= 1) v += __shfl_xor_sync(0xffffffffu, v, off);
        if (lane == 0) red[w] = v;
        __syncthreads();
        if (t == 0) {
            float s = 0.f;
#pragma unroll
            for (int i = 0; i < 16; i++) s += red[i];
            rs2[1] = s;
            float vo = bv2[0];
#pragma unroll
            for (int k = 0; k < 64; k++) vo += hred[k];
            out[BATCH * ASL + b] = vo;
        }
        __syncthreads();
        if (t < ASL) out[b * ASL + t] = e / rs2[1];
    }
}

extern "C" void kernel_launch(void* const* d_in, const int* in_sizes, int n_in,
                              void* d_out, int out_size) {
    const float* nf   = (const float*)d_in[0];
    const float* spec = (const float*)d_in[1];
    const float* mask = (const float*)d_in[3];
    const int*   imask= (const int*)  d_in[4];
    const float* W1   = (const float*)d_in[5];
    const float* b1   = (const float*)d_in[6];
    const float* W2   = (const float*)d_in[7];
    const float* b2   = (const float*)d_in[8];
    const float* Wv1  = (const float*)d_in[9];
    const float* bv1  = (const float*)d_in[10];
    const float* Wv2  = (const float*)d_in[11];
    const float* bv2  = (const float*)d_in[12];
    const float* Wa2  = (const float*)d_in[13];
    const float* ba2  = (const float*)d_in[14];
    const float* Wf   = (const float*)d_in[15];
    const float* bf   = (const float*)d_in[16];
    float* out = (float*)d_out;

    fused_kernel<<<NB, THREADS>>>(nf, spec, mask, imask, W1, b1, W2, b2,
                                  Wv1, bv1, Wv2, bv2, Wa2, ba2, Wf, bf, out);
}

// round 8
// speedup vs baseline: 1.4928x; 1.3782x over previous
#include <cuda_runtime.h>
#include <math.h>

#define NB 148
#define THREADS 512
#define BATCH 64
#define NPG 9
#define NTOT (BATCH*NPG)   // 576
#define H 128
#define K1 1801
#define O1 900
#define O2 100
#define ASL 243
#define NT1 15             // 15 n-tiles x 64 outs
#define KS1 9
#define KC1 201            // 9*201 = 1809 >= 1801
#define KS2 16
#define KC2 57             // 16*57 = 912 >= 900

// scratch (no allocation allowed)
__device__ float g_s1_part[KS1 * BATCH * O1];
__device__ float g_s2_part[KS2 * BATCH * O2];
__device__ float g_Ai[NTOT * H];
__device__ float g_Bj[NTOT * H];
__device__ unsigned g_count = 0;
__device__ unsigned g_gen = 0;

__device__ __forceinline__ void grid_barrier() {
    __syncthreads();
    __threadfence();
    if (threadIdx.x == 0) {
        unsigned gen = *(volatile unsigned*)&g_gen;
        if (atomicAdd(&g_count, 1u) == NB - 1) {
            g_count = 0;
            __threadfence();
            atomicAdd(&g_gen, 1u);
        } else {
            while (*(volatile unsigned*)&g_gen == gen) __nanosleep(32);
        }
    }
    __syncthreads();
}

// One 32-row x 64-col tile of [Ai|Bj] = relu(nf) @ Wa2[0:256 rows]  (512 thr)
__device__ __forceinline__ void ab_task(int task, int t, float* buf,
                                        const float* __restrict__ nf,
                                        const float* __restrict__ Wa2) {
    float (*As)[128] = (float (*)[128])buf;            // 32x128
    float (*Bs)[64]  = (float (*)[64])(buf + 4096);    // 128x64
    const int mt = task % 18, nty = task / 18;
    const int m0 = mt * 32;
    const int n0 = nty * 64;
    const int woff = (nty >= 2) ? (H * H - H) : 0;
    for (int idx = t; idx < 32 * 128; idx += THREADS) {
        int r = idx >> 7, k = idx & 127;
        As[r][k] = fmaxf(nf[(m0 + r) * H + k], 0.f);
    }
    for (int idx = t; idx < 128 * 64; idx += THREADS) {
        int k = idx >> 6, c = idx & 63;
        Bs[k][c] = Wa2[k * H + n0 + c + woff];
    }
    __syncthreads();
    const int c = t & 63, r0 = t >> 6;   // 8 row groups, rows r0+8i
    float acc[4] = {0.f, 0.f, 0.f, 0.f};
#pragma unroll 8
    for (int k = 0; k < 128; k += 4) {
        float b0v = Bs[k][c], b1v = Bs[k + 1][c];
        float b2v = Bs[k + 2][c], b3v = Bs[k + 3][c];
#pragma unroll
        for (int i = 0; i < 4; i++) {
            float4 a = *(const float4*)&As[r0 + 8 * i][k];
            acc[i] += a.x * b0v + a.y * b1v + a.z * b2v + a.w * b3v;
        }
    }
    float* dst = (nty < 2) ? g_Ai : g_Bj;
    const int col = (nty < 2) ? (n0 + c) : (n0 - 128 + c);
#pragma unroll
    for (int i = 0; i < 4; i++)
        dst[(m0 + r0 + 8 * i) * H + col] = acc[i];
}

__global__ __launch_bounds__(THREADS, 1)
void fused_kernel(const float* __restrict__ nf, const float* __restrict__ spec,
                  const float* __restrict__ mask, const int* __restrict__ imask,
                  const float* __restrict__ W1, const float* __restrict__ b1,
                  const float* __restrict__ W2, const float* __restrict__ b2,
                  const float* __restrict__ Wv1, const float* __restrict__ bv1,
                  const float* __restrict__ Wv2, const float* __restrict__ bv2,
                  const float* __restrict__ Wa2, const float* __restrict__ ba2,
                  const float* __restrict__ Wf, const float* __restrict__ bf,
                  float* __restrict__ out) {
    __shared__ __align__(16) float buf[12288];   // 48KB, reused per phase
    const int t = threadIdx.x;
    const int bid = blockIdx.x;

    // ===== Phase 1: gemm1 (135 blocks, reg-prefetch) + 13 ab tasks ===== (R5 proven)
    if (bid < NT1 * KS1) {
        const int nt = bid / KS1, ks = bid % KS1;
        const int og = t & 31;
        const int bg = t >> 5;
        const int o0 = nt * 64 + og * 2;
        const int b0 = bg * 4;
        const int kbeg = ks * KC1;
        const int kend = min(kbeg + KC1, K1);
        const int nch = (kend - kbeg + 31) >> 5;
        float* sp = buf;                     // [32][68]
        float* wt = buf + 32 * 68;           // [32][68]

        const int kk_s = t & 31;
        const int bb_s = t >> 5;
        const int kk_w = t >> 6;
        const int oo_w = t & 63;
        const int ow_g = nt * 64 + oo_w;
        const bool wok = (ow_g < O1);

        float rsv[4], rwv[4];
        {
            const int k0 = kbeg;
            const int klen = kend - k0;
#pragma unroll
            for (int j = 0; j < 4; j++)
                rsv[j] = (kk_s < klen) ? spec[(bb_s + 16 * j) * K1 + k0 + kk_s] : 0.f;
#pragma unroll
            for (int j = 0; j < 4; j++) {
                int kk = kk_w + 8 * j;
                rwv[j] = (kk < klen && wok) ? W1[(k0 + kk) * O1 + ow_g] : 0.f;
            }
        }
        float a00 = 0.f, a01 = 0.f, a10 = 0.f, a11 = 0.f;
        float a20 = 0.f, a21 = 0.f, a30 = 0.f, a31 = 0.f;

        for (int c = 0; c < nch; c++) {
            __syncthreads();
#pragma unroll
            for (int j = 0; j < 4; j++)
                sp[kk_s * 68 + bb_s + 16 * j] = rsv[j];
#pragma unroll
            for (int j = 0; j < 4; j++)
                wt[(kk_w + 8 * j) * 68 + oo_w] = rwv[j];
            __syncthreads();
            if (c + 1 < nch) {
                const int k0 = kbeg + (c + 1) * 32;
                const int klen = kend - k0;
#pragma unroll
                for (int j = 0; j < 4; j++)
                    rsv[j] = (kk_s < klen) ? spec[(bb_s + 16 * j) * K1 + k0 + kk_s] : 0.f;
#pragma unroll
                for (int j = 0; j < 4; j++) {
                    int kk = kk_w + 8 * j;
                    rwv[j] = (kk < klen && wok) ? W1[(k0 + kk) * O1 + ow_g] : 0.f;
                }
            }
#pragma unroll
            for (int kk = 0; kk < 32; kk++) {
                float4 s4 = *(const float4*)(sp + kk * 68 + b0);
                float2 w2 = *(const float2*)(wt + kk * 68 + og * 2);
                a00 += s4.x * w2.x; a01 += s4.x * w2.y;
                a10 += s4.y * w2.x; a11 += s4.y * w2.y;
                a20 += s4.z * w2.x; a21 += s4.z * w2.y;
                a30 += s4.w * w2.x; a31 += s4.w * w2.y;
            }
        }
        float* dst = g_s1_part + ks * (BATCH * O1);
        if (o0 + 1 < O1) {
            dst[(b0 + 0) * O1 + o0] = a00; dst[(b0 + 0) * O1 + o0 + 1] = a01;
            dst[(b0 + 1) * O1 + o0] = a10; dst[(b0 + 1) * O1 + o0 + 1] = a11;
            dst[(b0 + 2) * O1 + o0] = a20; dst[(b0 + 2) * O1 + o0 + 1] = a21;
            dst[(b0 + 3) * O1 + o0] = a30; dst[(b0 + 3) * O1 + o0 + 1] = a31;
        } else if (o0 < O1) {
            dst[(b0 + 0) * O1 + o0] = a00;
            dst[(b0 + 1) * O1 + o0] = a10;
            dst[(b0 + 2) * O1 + o0] = a20;
            dst[(b0 + 3) * O1 + o0] = a30;
        }
    } else {
        ab_task(bid - NT1 * KS1, t, buf, nf, Wa2);   // tasks 0..12
    }

    grid_barrier();

    // ===== Phase 2: gemm2 with W2 staged in smem (blocks 0-63) + ab 13-71 =====
    if (bid < 64) {
        const int nt = bid & 3, ks = bid >> 2;
        const int o = nt * 32 + (t & 31);
        const int bg = t >> 5;
        const int b0 = bg * 4;
        const int kbeg = ks * KC2;
        const int kend = min(kbeg + KC2, O1);
        const int klen = kend - kbeg;
        float* s1r = buf;                         // [64][60]
        float* w2s = buf + 3840;                  // [57][33]
        // stage W2 tile cooperatively (coalesced, parallel)
        for (int idx = t; idx < KC2 * 32; idx += THREADS) {
            int row = idx >> 5, col = idx & 31;
            int go = nt * 32 + col;
            w2s[row * 33 + col] = (row < klen && go < O2)
                                  ? W2[(kbeg + row) * O2 + go] : 0.f;
        }
        // reduce split-K gemm1 + bias + relu into smem
        for (int idx = t; idx < 64 * KC2; idx += THREADS) {
            int b = idx / KC2, kk = idx - b * KC2;
            float v = 0.f;
            if (kk < klen) {
                int gk = kbeg + kk;
                v = b1[gk];
#pragma unroll
                for (int c = 0; c < KS1; c++)
                    v += g_s1_part[c * (BATCH * O1) + b * O1 + gk];
                v = fmaxf(v, 0.f);
            }
            s1r[b * 60 + kk] = v;
        }
        __syncthreads();
        float acc[4] = {0.f, 0.f, 0.f, 0.f};
        const float* sb = s1r + b0 * 60;
        const int lane = t & 31;
#pragma unroll 4
        for (int kk = 0; kk < klen; kk++) {
            float w = w2s[kk * 33 + lane];
            acc[0] += sb[kk] * w;
            acc[1] += sb[60 + kk] * w;
            acc[2] += sb[120 + kk] * w;
            acc[3] += sb[180 + kk] * w;
        }
        if (o < O2) {
#pragma unroll
            for (int n = 0; n < 4; n++)
                g_s2_part[ks * (BATCH * O2) + (b0 + n) * O2 + o] = acc[n];
        }
    } else if (bid < 64 + 59) {
        ab_task(13 + (bid - 64), t, buf, nf, Wa2);   // tasks 13..71
    }

    grid_barrier();

    // ===== Phase 3: per-graph; all latency chains k-split over 512 threads =====
    if (bid < 64) {
        const int b = bid;
        const int lane = t & 31, w = t >> 5;
        float* ss   = buf;            // 100   [0,128)
        float* x    = buf + 128;      // 228   [128,384)
        float* Dc   = buf + 384;      // 128
        float* hred = buf + 512;      // 64
        float* As   = buf + 640;      // 9*132
        float* Bs   = buf + 1856;     // 9*132
        float* Wft  = buf + 3072;     // 384 (bond-major)
        float* fp2  = buf + 3456;     // 486
        float* fp   = buf + 3968;     // 243
        float* Dpart= buf + 4224;     // 512
        float* Vpart= buf + 4736;     // 512
        float* red  = buf + 5248;     // 16
        float* rs2  = buf + 5280;     // 2

        // ss = relu(b2 + sum_ks s2_part)   (16-way MLP)
        if (t < O2) {
            float a = b2[t];
#pragma unroll
            for (int c = 0; c < KS2; c++)
                a += g_s2_part[c * (BATCH * O2) + b * O2 + t];
            ss[t] = fmaxf(a, 0.f);
        }
        // stage As/Bs/Wft concurrently (coalesced, independent of ss)
        for (int idx = t; idx < NPG * H; idx += THREADS) {
            int i = idx >> 7, h = idx & 127;
            As[i * 132 + h] = g_Ai[(b * NPG + i) * H + h];
            Bs[i * 132 + h] = g_Bj[(b * NPG + i) * H + h];
        }
        for (int idx = t; idx < H * 3; idx += THREADS)
            Wft[(idx % 3) * H + idx / 3] = Wf[idx];
        if (t < H) {   // readout (9 coalesced loads, MLP 9)
            float sum = 0.f;
#pragma unroll
            for (int i = 0; i < NPG; i++) sum += nf[(b * NPG + i) * H + t];
            x[t] = sum;
        }
        __syncthreads();
        if (t >= H && t < H + O2) x[t] = ss[t - H];   // needs ss
        __syncthreads();

        // D partials: 128 outs x 4 k-splits of 25   (coalesced, MLP 25)
        {
            const int o = t & 127, q = t >> 7;
            const int kb = q * 25;
            float d = 0.f;
#pragma unroll
            for (int kk = 0; kk < 25; kk++)
                d += ss[kb + kk] * Wa2[(2 * H + kb + kk) * H + o];
            Dpart[q * H + o] = d;
        }
        // value partials: 64 outs x 8 k-splits of 29 (228 = 7*29+25)
        {
            const int o = t & 63, q = t >> 6;
            const int kb = q * 29;
            const int kl = min(29, 228 - kb);
            float v = 0.f;
            for (int kk = 0; kk < kl; kk++)
                v += x[kb + kk] * Wv1[(kb + kk) * 64 + o];
            Vpart[q * 64 + o] = v;
        }
        __syncthreads();
        if (t < H) {
            Dc[t] = ba2[t] + Dpart[t] + Dpart[H + t] + Dpart[2 * H + t] + Dpart[3 * H + t];
        }
        if (t < 64) {
            float a = bv1[t];
#pragma unroll
            for (int q = 0; q < 8; q++) a += Vpart[q * 64 + t];
            hred[t] = fmaxf(a, 0.f) * Wv2[t];
        }
        __syncthreads();

        // pair logits: 486 threads = 243 outputs x 2 h-halves
        if (t < 486) {
            const int half = (t >= ASL) ? 1 : 0;
            const int pi = t - ASL * half;
            const int pair = pi / 3, bond = pi - pair * 3;
            const int i = pair / NPG, j = pair - i * NPG;
            const float4* Ap = (const float4*)(As + i * 132) + half * 16;
            const float4* Bp = (const float4*)(Bs + j * 132) + half * 16;
            const float4* Dp = (const float4*)Dc + half * 16;
            const float4* Wp = (const float4*)(Wft + bond * H) + half * 16;
            float a = 0.f;
#pragma unroll
            for (int q = 0; q < 16; q++) {
                float4 av = Ap[q], bv = Bp[q], dv = Dp[q], wv = Wp[q];
                a += fmaxf(av.x + bv.x + dv.x, 0.f) * wv.x
                   + fmaxf(av.y + bv.y + dv.y, 0.f) * wv.y
                   + fmaxf(av.z + bv.z + dv.z, 0.f) * wv.z
                   + fmaxf(av.w + bv.w + dv.w, 0.f) * wv.w;
            }
            fp2[t] = a;
        }
        __syncthreads();
        if (t < ASL) fp[t] = fp2[t] + fp2[ASL + t] + bf[t % 3];
        __syncthreads();

        // gather + softmax
        float g = -INFINITY;
        if (t < ASL) g = fp[imask[b * ASL + t]] + mask[b * ASL + t];
        float v = g;
#pragma unroll
        for (int off = 16; off; off >>= 1) v = fmaxf(v, __shfl_xor_sync(0xffffffffu, v, off));
        if (lane == 0) red[w] = v;
        __syncthreads();
        if (t == 0) {
            float m = red[0];
#pragma unroll
            for (int i = 1; i < 16; i++) m = fmaxf(m, red[i]);
            rs2[0] = m;
        }
        __syncthreads();
        float e = (t < ASL) ? __expf(g - rs2[0]) : 0.f;
        v = e;
#pragma unroll
        for (int off = 16; off; off >>= 1) v += __shfl_xor_sync(0xffffffffu, v, off);
        if (lane == 0) red[w] = v;
        __syncthreads();
        if (t == 0) {
            float s = 0.f;
#pragma unroll
            for (int i = 0; i < 16; i++) s += red[i];
            rs2[1] = s;
            float vo = bv2[0];
#pragma unroll
            for (int k = 0; k < 64; k++) vo += hred[k];
            out[BATCH * ASL + b] = vo;
        }
        __syncthreads();
        if (t < ASL) out[b * ASL + t] = e / rs2[1];
    }
}

extern "C" void kernel_launch(void* const* d_in, const int* in_sizes, int n_in,
                              void* d_out, int out_size) {
    const float* nf   = (const float*)d_in[0];
    const float* spec = (const float*)d_in[1];
    const float* mask = (const float*)d_in[3];
    const int*   imask= (const int*)  d_in[4];
    const float* W1   = (const float*)d_in[5];
    const float* b1   = (const float*)d_in[6];
    const float* W2   = (const float*)d_in[7];
    const float* b2   = (const float*)d_in[8];
    const float* Wv1  = (const float*)d_in[9];
    const float* bv1  = (const float*)d_in[10];
    const float* Wv2  = (const float*)d_in[11];
    const float* bv2  = (const float*)d_in[12];
    const float* Wa2  = (const float*)d_in[13];
    const float* ba2  = (const float*)d_in[14];
    const float* Wf   = (const float*)d_in[15];
    const float* bf   = (const float*)d_in[16];
    float* out = (float*)d_out;

    fused_kernel<<<NB, THREADS>>>(nf, spec, mask, imask, W1, b1, W2, b2,
                                  Wv1, bv1, Wv2, bv2, Wa2, ba2, Wf, bf, out);
}